// round 5
// baseline (speedup 1.0000x reference)
#include <cuda_runtime.h>
#include <cuda_bf16.h>
#include <cstdint>

#define Bb   256
#define Nn   256
#define DIN  128
#define Hh   4
#define DHd  32
#define HID  128   // H*DH
#define NEG  0.2f
#define LNEPS 1e-5f
#define PAD  33
#define MTOT (Bb*Nn)   // 65536

// smem tile geometry for the MMA gemm
#define KS    136            // padded row length (bf16 elems): 272B row stride
#define TILEB (128*KS*2)     // 34816 bytes per 128x128 bf16 tile image
#define AH_OFF 0
#define AL_OFF TILEB
#define BH_OFF (2*TILEB)
#define BL_OFF (3*TILEB)
#define SMEM_GEMM (4*TILEB)  // 139264 bytes

// ---------------- scratch (device globals; no allocation allowed) ----------
__device__ float g_h[(size_t)MTOT * HID];      // x @ W1 (fp32)
__device__ float g_asrc[Bb * Hh * Nn];
__device__ float g_adst[Bb * Hh * Nn];
__device__ float4 g_part[Bb * Hh * Nn];        // per (b,head,node): {S1,S2,Sg,-}
__device__ float g_gw[HID];                    // gamma * W2
__device__ float g_cgw, g_cbw;                 // sum(gamma*W2), sum(beta*W2)
// W1^T bf16 hi/lo, padded [n][KS] image matching smem layout
__device__ __align__(16) __nv_bfloat16 g_whi[HID * KS];
__device__ __align__(16) __nv_bfloat16 g_wlo[HID * KS];

// ---------------- helpers ---------------------------------------------------
__device__ __forceinline__ uint32_t smem_u32(const void* p) {
    return (uint32_t)__cvta_generic_to_shared(p);
}
#define LDM4(r, a)                                                              \
    asm volatile("ldmatrix.sync.aligned.m8n8.x4.shared.b16 {%0,%1,%2,%3}, [%4];"\
                 : "=r"((r)[0]), "=r"((r)[1]), "=r"((r)[2]), "=r"((r)[3])       \
                 : "r"(a))
#define MMA(d, a, b0, b1)                                                       \
    asm volatile("mma.sync.aligned.m16n8k16.row.col.f32.bf16.bf16.f32 "        \
                 "{%0,%1,%2,%3},{%4,%5,%6,%7},{%8,%9},{%0,%1,%2,%3};"          \
                 : "+f"((d)[0]), "+f"((d)[1]), "+f"((d)[2]), "+f"((d)[3])       \
                 : "r"((a)[0]), "r"((a)[1]), "r"((a)[2]), "r"((a)[3]),          \
                   "r"(b0), "r"(b1))

// ---------------- kernel B: W1^T -> bf16 hi/lo image + LN/W2 constants -----
__global__ void __launch_bounds__(256) convW_kernel(const float* __restrict__ W1,
                                                    const float* __restrict__ gamma,
                                                    const float* __restrict__ beta,
                                                    const float* __restrict__ W2) {
    if (blockIdx.x < 64) {
        int g = blockIdx.x * 256 + threadIdx.x;   // 16384 elems
        int n = g >> 7, k = g & 127;
        float v = W1[(size_t)k * HID + n];
        __nv_bfloat16 h = __float2bfloat16(v);
        __nv_bfloat16 l = __float2bfloat16(v - __bfloat162float(h));
        g_whi[n * KS + k] = h;
        g_wlo[n * KS + k] = l;
    } else {
        __shared__ float rg[8], rb[8];
        int t = threadIdx.x;
        if (t < HID) {
            float w = W2[t];
            float gw = gamma[t] * w;
            float bw = beta[t] * w;
            g_gw[t] = gw;
#pragma unroll
            for (int off = 16; off; off >>= 1) {
                gw += __shfl_xor_sync(0xffffffffu, gw, off);
                bw += __shfl_xor_sync(0xffffffffu, bw, off);
            }
            if ((t & 31) == 0) { rg[t >> 5] = gw; rb[t >> 5] = bw; }
        }
        __syncthreads();
        if (t == 0) {
            g_cgw = rg[0] + rg[1] + rg[2] + rg[3];
            g_cbw = rb[0] + rb[1] + rb[2] + rb[3];
        }
    }
}

// ---------------- GEMM: h = x @ W1 (bf16 split, mma.sync) + fused attprep --
__global__ void __launch_bounds__(256, 1) gemm_kernel(const float* __restrict__ x,
                                                      const float* __restrict__ att_src,
                                                      const float* __restrict__ att_dst) {
    extern __shared__ __align__(16) uint8_t smem[];
    __nv_bfloat16* sAh = (__nv_bfloat16*)(smem + AH_OFF);
    __nv_bfloat16* sAl = (__nv_bfloat16*)(smem + AL_OFF);
    int tid = threadIdx.x, lane = tid & 31, wid = tid >> 5;
    int warpM = wid >> 2, warpN = wid & 3;

    {
        const uint4* wh = (const uint4*)g_whi;
        const uint4* wl = (const uint4*)g_wlo;
        uint4* dh = (uint4*)(smem + BH_OFF);
        uint4* dl = (uint4*)(smem + BL_OFF);
#pragma unroll
        for (int i = 0; i < 9; i++) {
            int idx = tid + i * 256;
            if (idx < TILEB / 16) { dh[idx] = wh[idx]; dl[idx] = wl[idx]; }
        }
    }
    {
        const float4* xp = (const float4*)(x + (size_t)blockIdx.x * 128 * DIN);
#pragma unroll
        for (int i = 0; i < 16; i++) {
            int idx = tid + i * 256;
            float4 v = xp[idx];
            int row = idx >> 5, c4 = (idx & 31) * 4;
            float f[4] = {v.x, v.y, v.z, v.w};
            __nv_bfloat16 h[4], l[4];
#pragma unroll
            for (int j = 0; j < 4; j++) {
                h[j] = __float2bfloat16(f[j]);
                l[j] = __float2bfloat16(f[j] - __bfloat162float(h[j]));
            }
            *(uint2*)&sAh[row * KS + c4] = *(const uint2*)h;
            *(uint2*)&sAl[row * KS + c4] = *(const uint2*)l;
        }
    }
    float asv[8], adv[8];
#pragma unroll
    for (int nt = 0; nt < 4; nt++)
#pragma unroll
        for (int j = 0; j < 2; j++) {
            int c = warpN * DHd + nt * 8 + (lane & 3) * 2 + j;
            asv[nt * 2 + j] = att_src[c];
            adv[nt * 2 + j] = att_dst[c];
        }
    __syncthreads();

    uint32_t sbase = smem_u32(smem);
    uint32_t aAddr = sbase + (uint32_t)(warpM * 64 * 272) +
                     (uint32_t)(((lane & 7) + ((lane >> 3) & 1) * 8) * 272 + (lane >> 4) * 16);
    uint32_t bAddr = sbase + (uint32_t)(warpN * 32 * 272) +
                     (uint32_t)(((lane & 7) + ((lane >> 4) & 1) * 8) * 272 + ((lane >> 3) & 1) * 16);

    float acc[4][4][4];
#pragma unroll
    for (int mt = 0; mt < 4; mt++)
#pragma unroll
        for (int nt = 0; nt < 4; nt++)
#pragma unroll
            for (int q = 0; q < 4; q++) acc[mt][nt][q] = 0.f;

    const uint32_t aSel[3] = {AH_OFF, AH_OFF, AL_OFF};
    const uint32_t bSel[3] = {BH_OFF, BL_OFF, BH_OFF};
#pragma unroll
    for (int t = 0; t < 3; t++) {
        uint32_t aT = aAddr + aSel[t];
        uint32_t bT = bAddr + bSel[t];
#pragma unroll
        for (int kc = 0; kc < 8; kc++) {
            uint32_t af[4][4], bf[2][4];
#pragma unroll
            for (int mt = 0; mt < 4; mt++) LDM4(af[mt], aT + mt * 4352 + kc * 32);
#pragma unroll
            for (int pp = 0; pp < 2; pp++) LDM4(bf[pp], bT + pp * 4352 + kc * 32);
#pragma unroll
            for (int mt = 0; mt < 4; mt++)
#pragma unroll
                for (int nt = 0; nt < 4; nt++)
                    MMA(acc[mt][nt], af[mt], bf[nt >> 1][(nt & 1) * 2],
                        bf[nt >> 1][(nt & 1) * 2 + 1]);
        }
    }

    int mbase = blockIdx.x * 128 + warpM * 64;
#pragma unroll
    for (int mt = 0; mt < 4; mt++)
#pragma unroll
        for (int half = 0; half < 2; half++) {
            int m = mbase + mt * 16 + half * 8 + (lane >> 2);
            float* hrow = g_h + (size_t)m * HID + warpN * DHd;
            float ps = 0.f, pd = 0.f;
#pragma unroll
            for (int nt = 0; nt < 4; nt++) {
                float v0 = acc[mt][nt][half * 2 + 0];
                float v1 = acc[mt][nt][half * 2 + 1];
                *(float2*)(hrow + nt * 8 + (lane & 3) * 2) = make_float2(v0, v1);
                ps = fmaf(v0, asv[nt * 2], fmaf(v1, asv[nt * 2 + 1], ps));
                pd = fmaf(v0, adv[nt * 2], fmaf(v1, adv[nt * 2 + 1], pd));
            }
            ps += __shfl_xor_sync(0xffffffffu, ps, 1);
            ps += __shfl_xor_sync(0xffffffffu, ps, 2);
            pd += __shfl_xor_sync(0xffffffffu, pd, 1);
            pd += __shfl_xor_sync(0xffffffffu, pd, 2);
            if ((lane & 3) == 0) {
                int b = m >> 8, n = m & 255;
                g_asrc[(b * Hh + warpN) * Nn + n] = ps;
                g_adst[(b * Hh + warpN) * Nn + n] = pd;
            }
        }
}

// ---------------- kernel 3: attn1 + fused LN-partials ----------------------
// Sorted prefix/suffix trick (exact); 8-warp chunked scans reading g_h rows
// directly (coalesced 128B, L2-resident) -> ~77KB smem -> 2 CTAs/SM.
__global__ void __launch_bounds__(256) attn1_kernel(const float* __restrict__ b1) {
    extern __shared__ float sm[];
    float* sv    = sm;                       // 256
    float* ev1   = sv + 256;                 // 256
    float* ev2   = ev1 + 256;                // 256
    float* SufS  = ev2 + 256;                // 257 (chunk-local scalar suffix)
    float* PreS  = SufS + 257;               // 257 (chunk-local scalar excl prefix)
    float* OffS1 = PreS + 257;               // 9
    float* OffS2 = OffS1 + 9;                // 9
    float* cS1   = OffS2 + 9;                // 8
    float* cS2   = cS1 + 8;                  // 8
    float* SufA  = cS2 + 8;                  // 257*PAD (chunk-local)
    float* PreB  = SufA + 257 * PAD;         // 257*PAD (chunk-local)
    float* Off1  = PreB + 257 * PAD;         // 9*PAD
    float* Off2  = Off1 + 9 * PAD;           // 9*PAD
    float* cT1   = Off2 + 9 * PAD;           // 8*PAD
    float* cT2   = cT1 + 8 * PAD;            // 8*PAD
    float* sgw   = cT2 + 8 * PAD;            // 32
    float* sb1h  = sgw + 32;                 // 32
    int*   sidx  = (int*)(sb1h + 32);        // 256

    int bh = blockIdx.x;
    int b = bh >> 2, hd = bh & 3;
    int tid = threadIdx.x, lane = tid & 31, w = tid >> 5;

    float v = g_asrc[bh * Nn + tid];
    SufA[tid] = v;                            // raw-v scratch (overwritten later)
    if (tid < 32) { sgw[tid] = g_gw[hd * DHd + tid]; sb1h[tid] = b1[hd * DHd + tid]; }
    __syncthreads();

    int cnt = 0;
#pragma unroll 8
    for (int j = 0; j < Nn; j++) {
        float ww = SufA[j];
        cnt += (ww < v) || (ww == v && j < tid);
    }
    sv[cnt] = v;
    sidx[cnt] = tid;
    __syncthreads();

    ev1[tid] = __expf(sv[tid]);
    ev2[tid] = __expf(NEG * sv[tid]);
    __syncthreads();

    // --- chunked scans: warp w owns rows [32w, 32w+32), lane = dim d ---
    const float* hbase = g_h + ((size_t)b * Nn) * HID + hd * DHd;
    {
        int base = w * 32, d = lane;
        float acc = 0.f, accS = 0.f;
#pragma unroll
        for (int i = 31; i >= 0; i--) {
            int r = base + i;
            float e = ev1[r];
            acc = fmaf(e, hbase[(size_t)sidx[r] * HID + d], acc);
            accS += e;
            SufA[r * PAD + d] = acc;
            if (d == 0) SufS[r] = accS;
        }
        cT1[w * PAD + d] = acc;
        if (d == 0) cS1[w] = accS;
        float acc2 = 0.f, accS2 = 0.f;
#pragma unroll
        for (int i = 0; i < 32; i++) {
            int r = base + i;
            PreB[r * PAD + d] = acc2;
            if (d == 0) PreS[r] = accS2;
            float e = ev2[r];
            acc2 = fmaf(e, hbase[(size_t)sidx[r] * HID + d], acc2);
            accS2 += e;
        }
        cT2[w * PAD + d] = acc2;
        if (d == 0) cS2[w] = accS2;
    }
    __syncthreads();

    // --- offsets table (9 chunks x 32 dims) + row-256 zeros + scalars ---
    for (int it = tid; it < 9 * 32; it += 256) {
        int c = it >> 5, d = it & 31;
        float s1 = 0.f, s2 = 0.f;
        for (int c2 = c + 1; c2 < 8; c2++) s1 += cT1[c2 * PAD + d];
        for (int c2 = 0; c2 < c && c2 < 8; c2++) s2 += cT2[c2 * PAD + d];
        Off1[c * PAD + d] = s1;
        Off2[c * PAD + d] = s2;
    }
    if (tid < PAD) { SufA[256 * PAD + tid] = 0.f; PreB[256 * PAD + tid] = 0.f; }
    if (tid < 9) {
        float s1 = 0.f, s2 = 0.f;
        for (int c2 = tid + 1; c2 < 8; c2++) s1 += cS1[c2];
        for (int c2 = 0; c2 < tid && c2 < 8; c2++) s2 += cS2[c2];
        OffS1[tid] = s1;
        OffS2[tid] = s2;
    }
    if (tid == 0) { SufS[256] = 0.f; PreS[256] = 0.f; }
    __syncthreads();

    // --- query: node i = tid ---
    float u = g_adst[bh * Nn + tid];
    float t = -u;
    int lo = 0, hi = 256;
    while (lo < hi) {
        int mid = (lo + hi) >> 1;
        if (sv[mid] <= t) lo = mid + 1; else hi = mid;
    }
    int k = lo, c = k >> 5;
    float e1 = __expf(u), e2 = __expf(NEG * u);
    float den = e1 * (SufS[k] + OffS1[c]) + e2 * (PreS[k] + OffS2[c]);
    float inv = 1.f / den;
    float s1 = 0.f, s2 = 0.f, sg = 0.f;
#pragma unroll
    for (int d = 0; d < DHd; d++) {
        float num = e1 * (SufA[k * PAD + d] + Off1[c * PAD + d]) +
                    e2 * (PreB[k * PAD + d] + Off2[c * PAD + d]);
        float o = fmaf(num, inv, sb1h[d]);
        s1 += o;
        s2 = fmaf(o, o, s2);
        sg = fmaf(o, sgw[d], sg);
    }
    g_part[bh * Nn + tid] = make_float4(s1, s2, sg, 0.f);
}

// ---------------- kernel 4: LN-finish + layer-2 attention (sorted) + ELU ---
// Same rank-1 trick as layer 1 but values are scalars: O(N sort + log N).
__global__ void __launch_bounds__(256) attn2_kernel(const float* __restrict__ att_src2,
                                                    const float* __restrict__ att_dst2,
                                                    const float* __restrict__ b2,
                                                    float* __restrict__ out) {
    __shared__ float h2s[256], vraw[256], sv[256], ev1s[256], ev2s[256];
    __shared__ float SufN[257], SufD[257], PreN[257], PreD[257];
    __shared__ float cN1[8], cD1[8], cN2[8], cD2[8];
    __shared__ float OffN1[9], OffD1[9], OffN2[9], OffD2[9];
    __shared__ int sidx[256];
    int b = blockIdx.x, i = threadIdx.x, lane = i & 31, w = i >> 5;

    // LN finish
    float s1 = 0.f, s2 = 0.f, sg = 0.f;
#pragma unroll
    for (int hd = 0; hd < Hh; hd++) {
        float4 p = g_part[(b * Hh + hd) * Nn + i];
        s1 += p.x; s2 += p.y; sg += p.z;
    }
    float mu = s1 * (1.f / 128.f);
    float var = s2 * (1.f / 128.f) - mu * mu;
    float rstd = rsqrtf(var + LNEPS);
    float h2i = rstd * (sg - mu * g_cgw) + g_cbw;

    float asrc = att_src2[0], adst = att_dst2[0];
    float vv = asrc * h2i;
    h2s[i] = h2i;
    vraw[i] = vv;
    __syncthreads();

    // rank sort of v
    int cnt = 0;
#pragma unroll 8
    for (int j = 0; j < Nn; j++) {
        float ww = vraw[j];
        cnt += (ww < vv) || (ww == vv && j < i);
    }
    sv[cnt] = vv;
    sidx[cnt] = i;
    __syncthreads();

    ev1s[i] = __expf(sv[i]);
    ev2s[i] = __expf(NEG * sv[i]);
    __syncthreads();

    // chunked scalar scans (redundant across lanes; lane 0 stores)
    {
        int base = w * 32;
        float aN = 0.f, aD = 0.f;
#pragma unroll
        for (int q = 31; q >= 0; q--) {
            int r = base + q;
            float e = ev1s[r];
            aN = fmaf(e, h2s[sidx[r]], aN);
            aD += e;
            if (lane == 0) { SufN[r] = aN; SufD[r] = aD; }
        }
        if (lane == 0) { cN1[w] = aN; cD1[w] = aD; }
        float bN = 0.f, bD = 0.f;
#pragma unroll
        for (int q = 0; q < 32; q++) {
            int r = base + q;
            if (lane == 0) { PreN[r] = bN; PreD[r] = bD; }
            float e = ev2s[r];
            bN = fmaf(e, h2s[sidx[r]], bN);
            bD += e;
        }
        if (lane == 0) { cN2[w] = bN; cD2[w] = bD; }
    }
    __syncthreads();

    if (i < 9) {
        float n1 = 0.f, d1 = 0.f, n2 = 0.f, d2 = 0.f;
        for (int c2 = i + 1; c2 < 8; c2++) { n1 += cN1[c2]; d1 += cD1[c2]; }
        for (int c2 = 0; c2 < i && c2 < 8; c2++) { n2 += cN2[c2]; d2 += cD2[c2]; }
        OffN1[i] = n1; OffD1[i] = d1; OffN2[i] = n2; OffD2[i] = d2;
    }
    if (i == 9) { SufN[256] = 0.f; SufD[256] = 0.f; PreN[256] = 0.f; PreD[256] = 0.f; }
    __syncthreads();

    // query
    float u = adst * h2i;
    float t = -u;
    int lo = 0, hi = 256;
    while (lo < hi) {
        int mid = (lo + hi) >> 1;
        if (sv[mid] <= t) lo = mid + 1; else hi = mid;
    }
    int k = lo, c = k >> 5;
    float e1 = __expf(u), e2 = __expf(NEG * u);
    float num = e1 * (SufN[k] + OffN1[c]) + e2 * (PreN[k] + OffN2[c]);
    float den = e1 * (SufD[k] + OffD1[c]) + e2 * (PreD[k] + OffD2[c]);
    float o = num / den + b2[0];
    out[b * Nn + i] = o > 0.f ? o : expm1f(o);
}

// ---------------------------------------------------------------------------
static const int SMEM3_BYTES =
    (int)((256 * 3 + 257 * 2 + 9 * 2 + 8 * 2 + 2 * 257 * PAD +
           2 * 9 * PAD + 2 * 8 * PAD + 64) * sizeof(float) + 256 * sizeof(int));

extern "C" void kernel_launch(void* const* d_in, const int* in_sizes, int n_in,
                              void* d_out, int out_size) {
    (void)in_sizes; (void)n_in; (void)out_size;
    const float* x        = (const float*)d_in[0];
    // d_in[1] = adj (unused; fully-connected graph)
    const float* W1       = (const float*)d_in[2];
    const float* b1       = (const float*)d_in[3];
    const float* att_src1 = (const float*)d_in[4];
    const float* att_dst1 = (const float*)d_in[5];
    const float* gamma    = (const float*)d_in[6];
    const float* beta     = (const float*)d_in[7];
    const float* W2       = (const float*)d_in[8];
    const float* b2       = (const float*)d_in[9];
    const float* att_src2 = (const float*)d_in[10];
    const float* att_dst2 = (const float*)d_in[11];
    float* out = (float*)d_out;

    cudaFuncSetAttribute(attn1_kernel,
                         cudaFuncAttributeMaxDynamicSharedMemorySize, SMEM3_BYTES);
    cudaFuncSetAttribute(gemm_kernel,
                         cudaFuncAttributeMaxDynamicSharedMemorySize, SMEM_GEMM);

    convW_kernel<<<65, 256>>>(W1, gamma, beta, W2);
    gemm_kernel<<<MTOT / 128, 256, SMEM_GEMM>>>(x, att_src1, att_dst1);
    attn1_kernel<<<Bb * Hh, 256, SMEM3_BYTES>>>(b1);
    attn2_kernel<<<Bb, 256>>>(att_src2, att_dst2, b2, out);
}

// round 6
// speedup vs baseline: 1.3020x; 1.3020x over previous
#include <cuda_runtime.h>
#include <cuda_bf16.h>
#include <cstdint>

#define Bb   256
#define Nn   256
#define DIN  128
#define Hh   4
#define DHd  32
#define HID  128   // H*DH
#define NEG  0.2f
#define LNEPS 1e-5f
#define PAD  33
#define MTOT (Bb*Nn)   // 65536

// smem tile geometry for the MMA gemm
#define KS    136            // padded row length (bf16 elems): 272B row stride
#define TILEB (128*KS*2)     // 34816 bytes per 128x128 bf16 tile image
#define AH_OFF 0
#define AL_OFF TILEB
#define BH_OFF (2*TILEB)
#define BL_OFF (3*TILEB)
#define SMEM_GEMM (4*TILEB)  // 139264 bytes

// ---------------- scratch (device globals; no allocation allowed) ----------
__device__ float g_h[(size_t)MTOT * HID];      // x @ W1 (fp32)
__device__ float g_asrc[Bb * Hh * Nn];
__device__ float g_adst[Bb * Hh * Nn];
__device__ float4 g_part[Bb * Hh * Nn];        // per (b,head,node): {S1,S2,Sg,-}
__device__ float g_gw[HID];                    // gamma * W2
__device__ float g_cgw, g_cbw;                 // sum(gamma*W2), sum(beta*W2)
// W1^T bf16 hi/lo, padded [n][KS] image matching smem layout
__device__ __align__(16) __nv_bfloat16 g_whi[HID * KS];
__device__ __align__(16) __nv_bfloat16 g_wlo[HID * KS];

// ---------------- helpers ---------------------------------------------------
__device__ __forceinline__ uint32_t smem_u32(const void* p) {
    return (uint32_t)__cvta_generic_to_shared(p);
}
#define LDM4(r, a)                                                              \
    asm volatile("ldmatrix.sync.aligned.m8n8.x4.shared.b16 {%0,%1,%2,%3}, [%4];"\
                 : "=r"((r)[0]), "=r"((r)[1]), "=r"((r)[2]), "=r"((r)[3])       \
                 : "r"(a))
#define MMA(d, a, b0, b1)                                                       \
    asm volatile("mma.sync.aligned.m16n8k16.row.col.f32.bf16.bf16.f32 "        \
                 "{%0,%1,%2,%3},{%4,%5,%6,%7},{%8,%9},{%0,%1,%2,%3};"          \
                 : "+f"((d)[0]), "+f"((d)[1]), "+f"((d)[2]), "+f"((d)[3])       \
                 : "r"((a)[0]), "r"((a)[1]), "r"((a)[2]), "r"((a)[3]),          \
                   "r"(b0), "r"(b1))

// ---------------- kernel B: W1^T -> bf16 hi/lo image + LN/W2 constants -----
__global__ void __launch_bounds__(256) convW_kernel(const float* __restrict__ W1,
                                                    const float* __restrict__ gamma,
                                                    const float* __restrict__ beta,
                                                    const float* __restrict__ W2) {
    if (blockIdx.x < 64) {
        int g = blockIdx.x * 256 + threadIdx.x;   // 16384 elems
        int n = g >> 7, k = g & 127;
        float v = W1[(size_t)k * HID + n];
        __nv_bfloat16 h = __float2bfloat16(v);
        __nv_bfloat16 l = __float2bfloat16(v - __bfloat162float(h));
        g_whi[n * KS + k] = h;
        g_wlo[n * KS + k] = l;
    } else {
        __shared__ float rg[8], rb[8];
        int t = threadIdx.x;
        if (t < HID) {
            float w = W2[t];
            float gw = gamma[t] * w;
            float bw = beta[t] * w;
            g_gw[t] = gw;
#pragma unroll
            for (int off = 16; off; off >>= 1) {
                gw += __shfl_xor_sync(0xffffffffu, gw, off);
                bw += __shfl_xor_sync(0xffffffffu, bw, off);
            }
            if ((t & 31) == 0) { rg[t >> 5] = gw; rb[t >> 5] = bw; }
        }
        __syncthreads();
        if (t == 0) {
            g_cgw = rg[0] + rg[1] + rg[2] + rg[3];
            g_cbw = rb[0] + rb[1] + rb[2] + rb[3];
        }
    }
}

// ---------------- GEMM: h = x @ W1 (bf16 split, mma.sync) + fused attprep --
__global__ void __launch_bounds__(256, 1) gemm_kernel(const float* __restrict__ x,
                                                      const float* __restrict__ att_src,
                                                      const float* __restrict__ att_dst) {
    extern __shared__ __align__(16) uint8_t smem[];
    __nv_bfloat16* sAh = (__nv_bfloat16*)(smem + AH_OFF);
    __nv_bfloat16* sAl = (__nv_bfloat16*)(smem + AL_OFF);
    int tid = threadIdx.x, lane = tid & 31, wid = tid >> 5;
    int warpM = wid >> 2, warpN = wid & 3;

    {
        const uint4* wh = (const uint4*)g_whi;
        const uint4* wl = (const uint4*)g_wlo;
        uint4* dh = (uint4*)(smem + BH_OFF);
        uint4* dl = (uint4*)(smem + BL_OFF);
#pragma unroll
        for (int i = 0; i < 9; i++) {
            int idx = tid + i * 256;
            if (idx < TILEB / 16) { dh[idx] = wh[idx]; dl[idx] = wl[idx]; }
        }
    }
    {
        const float4* xp = (const float4*)(x + (size_t)blockIdx.x * 128 * DIN);
#pragma unroll
        for (int i = 0; i < 16; i++) {
            int idx = tid + i * 256;
            float4 v = xp[idx];
            int row = idx >> 5, c4 = (idx & 31) * 4;
            float f[4] = {v.x, v.y, v.z, v.w};
            __nv_bfloat16 h[4], l[4];
#pragma unroll
            for (int j = 0; j < 4; j++) {
                h[j] = __float2bfloat16(f[j]);
                l[j] = __float2bfloat16(f[j] - __bfloat162float(h[j]));
            }
            *(uint2*)&sAh[row * KS + c4] = *(const uint2*)h;
            *(uint2*)&sAl[row * KS + c4] = *(const uint2*)l;
        }
    }
    float asv[8], adv[8];
#pragma unroll
    for (int nt = 0; nt < 4; nt++)
#pragma unroll
        for (int j = 0; j < 2; j++) {
            int c = warpN * DHd + nt * 8 + (lane & 3) * 2 + j;
            asv[nt * 2 + j] = att_src[c];
            adv[nt * 2 + j] = att_dst[c];
        }
    __syncthreads();

    uint32_t sbase = smem_u32(smem);
    uint32_t aAddr = sbase + (uint32_t)(warpM * 64 * 272) +
                     (uint32_t)(((lane & 7) + ((lane >> 3) & 1) * 8) * 272 + (lane >> 4) * 16);
    uint32_t bAddr = sbase + (uint32_t)(warpN * 32 * 272) +
                     (uint32_t)(((lane & 7) + ((lane >> 4) & 1) * 8) * 272 + ((lane >> 3) & 1) * 16);

    float acc[4][4][4];
#pragma unroll
    for (int mt = 0; mt < 4; mt++)
#pragma unroll
        for (int nt = 0; nt < 4; nt++)
#pragma unroll
            for (int q = 0; q < 4; q++) acc[mt][nt][q] = 0.f;

    const uint32_t aSel[3] = {AH_OFF, AH_OFF, AL_OFF};
    const uint32_t bSel[3] = {BH_OFF, BL_OFF, BH_OFF};
#pragma unroll
    for (int t = 0; t < 3; t++) {
        uint32_t aT = aAddr + aSel[t];
        uint32_t bT = bAddr + bSel[t];
#pragma unroll
        for (int kc = 0; kc < 8; kc++) {
            uint32_t af[4][4], bf[2][4];
#pragma unroll
            for (int mt = 0; mt < 4; mt++) LDM4(af[mt], aT + mt * 4352 + kc * 32);
#pragma unroll
            for (int pp = 0; pp < 2; pp++) LDM4(bf[pp], bT + pp * 4352 + kc * 32);
#pragma unroll
            for (int mt = 0; mt < 4; mt++)
#pragma unroll
                for (int nt = 0; nt < 4; nt++)
                    MMA(acc[mt][nt], af[mt], bf[nt >> 1][(nt & 1) * 2],
                        bf[nt >> 1][(nt & 1) * 2 + 1]);
        }
    }

    int mbase = blockIdx.x * 128 + warpM * 64;
#pragma unroll
    for (int mt = 0; mt < 4; mt++)
#pragma unroll
        for (int half = 0; half < 2; half++) {
            int m = mbase + mt * 16 + half * 8 + (lane >> 2);
            float* hrow = g_h + (size_t)m * HID + warpN * DHd;
            float ps = 0.f, pd = 0.f;
#pragma unroll
            for (int nt = 0; nt < 4; nt++) {
                float v0 = acc[mt][nt][half * 2 + 0];
                float v1 = acc[mt][nt][half * 2 + 1];
                *(float2*)(hrow + nt * 8 + (lane & 3) * 2) = make_float2(v0, v1);
                ps = fmaf(v0, asv[nt * 2], fmaf(v1, asv[nt * 2 + 1], ps));
                pd = fmaf(v0, adv[nt * 2], fmaf(v1, adv[nt * 2 + 1], pd));
            }
            ps += __shfl_xor_sync(0xffffffffu, ps, 1);
            ps += __shfl_xor_sync(0xffffffffu, ps, 2);
            pd += __shfl_xor_sync(0xffffffffu, pd, 1);
            pd += __shfl_xor_sync(0xffffffffu, pd, 2);
            if ((lane & 3) == 0) {
                int b = m >> 8, n = m & 255;
                g_asrc[(b * Hh + warpN) * Nn + n] = ps;
                g_adst[(b * Hh + warpN) * Nn + n] = pd;
            }
        }
}

// ---------------- kernel 3: attn1 + fused LN-partials (R4 version) ---------
__global__ void __launch_bounds__(256) attn1_kernel(const float* __restrict__ b1) {
    extern __shared__ float sm[];
    float* sv    = sm;                       // 256
    float* ev1   = sv + 256;                 // 256
    float* ev2   = ev1 + 256;                // 256
    float* SufS  = ev2 + 256;                // 257
    float* PreS  = SufS + 257;               // 257
    float* OffS1 = PreS + 257;               // 9
    float* OffS2 = OffS1 + 9;                // 9
    float* cS1   = OffS2 + 9;                // 8
    float* cS2   = cS1 + 8;                  // 8
    float* hs    = cS2 + 8;                  // 256*PAD
    float* SufA  = hs + 256 * PAD;           // 257*PAD
    float* PreB  = SufA + 257 * PAD;         // 257*PAD
    float* Off1  = PreB + 257 * PAD;         // 9*PAD
    float* Off2  = Off1 + 9 * PAD;           // 9*PAD
    float* cT1   = Off2 + 9 * PAD;           // 8*PAD
    float* cT2   = cT1 + 8 * PAD;            // 8*PAD
    float* sgw   = cT2 + 8 * PAD;            // 32
    float* sb1h  = sgw + 32;                 // 32
    int*   sidx  = (int*)(sb1h + 32);        // 256

    int bh = blockIdx.x;
    int b = bh >> 2, hd = bh & 3;
    int tid = threadIdx.x, lane = tid & 31, w = tid >> 5;

    float v = g_asrc[bh * Nn + tid];
    SufA[tid] = v;
    __syncthreads();

    int cnt = 0;
#pragma unroll 8
    for (int j = 0; j < Nn; j++) {
        float ww = SufA[j];
        cnt += (ww < v) || (ww == v && j < tid);
    }
    sv[cnt] = v;
    sidx[cnt] = tid;

    for (int idx = tid; idx < Nn * DHd; idx += 256) {
        int j = idx >> 5, d = idx & 31;
        hs[j * PAD + d] = g_h[((size_t)(b * Nn + j)) * HID + hd * DHd + d];
    }
    if (tid < 32) { sgw[tid] = g_gw[hd * DHd + tid]; sb1h[tid] = b1[hd * DHd + tid]; }
    __syncthreads();

    ev1[tid] = __expf(sv[tid]);
    ev2[tid] = __expf(NEG * sv[tid]);
    __syncthreads();

    // --- chunked scans: warp w owns rows [32w, 32w+32), lane = dim d ---
    {
        int base = w * 32, d = lane;
        float acc = 0.f, accS = 0.f;
#pragma unroll
        for (int i = 31; i >= 0; i--) {
            int r = base + i;
            float e = ev1[r];
            acc = fmaf(e, hs[sidx[r] * PAD + d], acc);
            accS += e;
            SufA[r * PAD + d] = acc;
            if (d == 0) SufS[r] = accS;
        }
        cT1[w * PAD + d] = acc;
        if (d == 0) cS1[w] = accS;
        float acc2 = 0.f, accS2 = 0.f;
#pragma unroll
        for (int i = 0; i < 32; i++) {
            int r = base + i;
            PreB[r * PAD + d] = acc2;
            if (d == 0) PreS[r] = accS2;
            float e = ev2[r];
            acc2 = fmaf(e, hs[sidx[r] * PAD + d], acc2);
            accS2 += e;
        }
        cT2[w * PAD + d] = acc2;
        if (d == 0) cS2[w] = accS2;
    }
    __syncthreads();

    // --- offsets table (9 chunks x 32 dims) + row-256 zeros + scalars ---
    for (int it = tid; it < 9 * 32; it += 256) {
        int c = it >> 5, d = it & 31;
        float s1 = 0.f, s2 = 0.f;
        for (int c2 = c + 1; c2 < 8; c2++) s1 += cT1[c2 * PAD + d];
        for (int c2 = 0; c2 < c && c2 < 8; c2++) s2 += cT2[c2 * PAD + d];
        Off1[c * PAD + d] = s1;
        Off2[c * PAD + d] = s2;
    }
    if (tid < PAD) { SufA[256 * PAD + tid] = 0.f; PreB[256 * PAD + tid] = 0.f; }
    if (tid < 9) {
        float s1 = 0.f, s2 = 0.f;
        for (int c2 = tid + 1; c2 < 8; c2++) s1 += cS1[c2];
        for (int c2 = 0; c2 < tid && c2 < 8; c2++) s2 += cS2[c2];
        OffS1[tid] = s1;
        OffS2[tid] = s2;
    }
    if (tid == 0) { SufS[256] = 0.f; PreS[256] = 0.f; }
    __syncthreads();

    // --- query: node i = tid ---
    float u = g_adst[bh * Nn + tid];
    float t = -u;
    int lo = 0, hi = 256;
    while (lo < hi) {
        int mid = (lo + hi) >> 1;
        if (sv[mid] <= t) lo = mid + 1; else hi = mid;
    }
    int k = lo, c = k >> 5;
    float e1 = __expf(u), e2 = __expf(NEG * u);
    float den = e1 * (SufS[k] + OffS1[c]) + e2 * (PreS[k] + OffS2[c]);
    float inv = 1.f / den;
    float s1 = 0.f, s2 = 0.f, sg = 0.f;
#pragma unroll
    for (int d = 0; d < DHd; d++) {
        float num = e1 * (SufA[k * PAD + d] + Off1[c * PAD + d]) +
                    e2 * (PreB[k * PAD + d] + Off2[c * PAD + d]);
        float o = fmaf(num, inv, sb1h[d]);
        s1 += o;
        s2 = fmaf(o, o, s2);
        sg = fmaf(o, sgw[d], sg);
    }
    g_part[bh * Nn + tid] = make_float4(s1, s2, sg, 0.f);
}

// ---------------- kernel 4: LN-finish + layer-2 attention + ELU ------------
// j-loop split across 4 warp-groups (1024 threads): occ 20% -> ~80%,
// per-thread serial exp chain 256 -> 64.
__global__ void __launch_bounds__(1024) attn2_kernel(const float* __restrict__ att_src2,
                                                     const float* __restrict__ att_dst2,
                                                     const float* __restrict__ b2,
                                                     float* __restrict__ out) {
    __shared__ float h2s[256], vj[256];
    __shared__ float pnum[4][256], pden[4][256];
    int b = blockIdx.x, t = threadIdx.x;
    int i = t & 255, q = t >> 8;
    float asrc = att_src2[0], adst = att_dst2[0];

    if (q == 0) {
        float s1 = 0.f, s2 = 0.f, sg = 0.f;
#pragma unroll
        for (int hd = 0; hd < Hh; hd++) {
            float4 p = g_part[(b * Hh + hd) * Nn + i];
            s1 += p.x; s2 += p.y; sg += p.z;
        }
        float mu = s1 * (1.f / 128.f);
        float var = s2 * (1.f / 128.f) - mu * mu;
        float rstd = rsqrtf(var + LNEPS);
        float h2i = rstd * (sg - mu * g_cgw) + g_cbw;
        h2s[i] = h2i;
        vj[i] = asrc * h2i;
    }
    __syncthreads();

    float u = adst * h2s[i];
    float num = 0.f, den = 0.f;
    int j0 = q * 64;
#pragma unroll 8
    for (int j = j0; j < j0 + 64; j++) {
        float e = u + vj[j];
        e = e > 0.f ? e : NEG * e;
        float w = __expf(e);
        den += w;
        num = fmaf(w, h2s[j], num);
    }
    pnum[q][i] = num;
    pden[q][i] = den;
    __syncthreads();

    if (q == 0) {
        float n = pnum[0][i] + pnum[1][i] + pnum[2][i] + pnum[3][i];
        float d = pden[0][i] + pden[1][i] + pden[2][i] + pden[3][i];
        float o = n / d + b2[0];
        out[b * Nn + i] = o > 0.f ? o : expm1f(o);
    }
}

// ---------------------------------------------------------------------------
static const int SMEM3_BYTES =
    (int)((256 * 3 + 257 * 2 + 9 * 2 + 8 * 2 + 256 * PAD + 2 * 257 * PAD +
           2 * 9 * PAD + 2 * 8 * PAD + 64) * sizeof(float) + 256 * sizeof(int));

extern "C" void kernel_launch(void* const* d_in, const int* in_sizes, int n_in,
                              void* d_out, int out_size) {
    (void)in_sizes; (void)n_in; (void)out_size;
    const float* x        = (const float*)d_in[0];
    // d_in[1] = adj (unused; fully-connected graph)
    const float* W1       = (const float*)d_in[2];
    const float* b1       = (const float*)d_in[3];
    const float* att_src1 = (const float*)d_in[4];
    const float* att_dst1 = (const float*)d_in[5];
    const float* gamma    = (const float*)d_in[6];
    const float* beta     = (const float*)d_in[7];
    const float* W2       = (const float*)d_in[8];
    const float* b2       = (const float*)d_in[9];
    const float* att_src2 = (const float*)d_in[10];
    const float* att_dst2 = (const float*)d_in[11];
    float* out = (float*)d_out;

    cudaFuncSetAttribute(attn1_kernel,
                         cudaFuncAttributeMaxDynamicSharedMemorySize, SMEM3_BYTES);
    cudaFuncSetAttribute(gemm_kernel,
                         cudaFuncAttributeMaxDynamicSharedMemorySize, SMEM_GEMM);

    convW_kernel<<<65, 256>>>(W1, gamma, beta, W2);
    gemm_kernel<<<MTOT / 128, 256, SMEM_GEMM>>>(x, att_src1, att_dst1);
    attn1_kernel<<<Bb * Hh, 256, SMEM3_BYTES>>>(b1);
    attn2_kernel<<<Bb, 1024>>>(att_src2, att_dst2, b2, out);
}